// round 16
// baseline (speedup 1.0000x reference)
#include <cuda_runtime.h>
#include <cuda_fp16.h>
#include <cstdint>

// Problem constants
constexpr int Bc  = 2;
constexpr int Sc  = 2048;
constexpr int Dc  = 1024;
constexpr int Hc  = 16;
constexpr int HDc = 64;
constexpr int Mc  = Bc * Sc;

// Scratch (__device__ globals). All fp16 packed as u32 (=2 fp16 along k),
// pair-interleaved within 16-k groups: pair j (j=0..7) at pos8(j)=2*(j&3)+(j>>2)
// so pairs {j, j+4} are adjacent -> fragment loads are single LDS.64.
__device__ uint32_t g_Q[Bc * Hc * Sc * HDc / 2];   // head-major, scaled by 0.125*log2e
__device__ uint32_t g_K[Bc * Hc * Sc * HDc / 2];   // head-major
__device__ uint32_t g_V[Bc * Hc * Sc * HDc / 2];   // TRANSPOSED [bh*64+hd][s]
__device__ uint32_t g_ctx[Mc * Dc / 2];
__device__ uint32_t g_qc[Mc * Dc / 2];             // converted inputs
__device__ uint32_t g_kc[Mc * Dc / 2];
__device__ uint32_t g_vc[Mc * Dc / 2];
__device__ uint32_t g_wq[Dc * Dc / 2];
__device__ uint32_t g_wk[Dc * Dc / 2];
__device__ uint32_t g_wv[Dc * Dc / 2];
__device__ uint32_t g_wo[Dc * Dc / 2];

extern __shared__ __align__(1024) char dyn_smem[];

// ---------------------------------------------------------------------------
// helpers
// ---------------------------------------------------------------------------
__device__ __forceinline__ uint32_t smem_u32(const void* p) {
    uint32_t a;
    asm("{ .reg .u64 t; cvta.to.shared.u64 t, %1; cvt.u32.u64 %0, t; }"
        : "=r"(a) : "l"(p));
    return a;
}

__device__ __forceinline__ uint32_t pack2(float a, float b) {
    __half2 h = __floats2half2_rn(a, b);
    return *reinterpret_cast<uint32_t*>(&h);
}

__device__ __forceinline__ void mma_f16(float* d, const uint32_t* a,
                                        const uint32_t* b) {
    asm volatile(
        "mma.sync.aligned.m16n8k16.row.col.f32.f16.f16.f32 "
        "{%0,%1,%2,%3}, {%4,%5,%6,%7}, {%8,%9}, {%0,%1,%2,%3};"
        : "+f"(d[0]), "+f"(d[1]), "+f"(d[2]), "+f"(d[3])
        : "r"(a[0]), "r"(a[1]), "r"(a[2]), "r"(a[3]), "r"(b[0]), "r"(b[1]));
}

__device__ __forceinline__ void cp_async16(uint32_t saddr, const void* g) {
    asm volatile("cp.async.cg.shared.global [%0], [%1], 16;"
                 :: "r"(saddr), "l"(g));
}
#define CP_COMMIT() asm volatile("cp.async.commit_group;" ::: "memory")
#define CP_WAIT0()  asm volatile("cp.async.wait_group 0;" ::: "memory")
#define CP_WAIT1()  asm volatile("cp.async.wait_group 1;" ::: "memory")

// ---------------------------------------------------------------------------
// Prepass: fp32 -> fp16 pairs, pair-interleaved (rows multiple of 16 elems)
// ---------------------------------------------------------------------------
struct CvtArgs {
    const float4* src[7];
    uint32_t*     dst[7];
    int           n4[7];
};

__global__ __launch_bounds__(256) void cvt_kernel(CvtArgs a)
{
    const int z = blockIdx.y;
    const float4* s = a.src[z];
    uint32_t* d = a.dst[z];
    const int n4 = a.n4[z];
    const int stride = gridDim.x * blockDim.x;
    for (int i = blockIdx.x * blockDim.x + threadIdx.x; i < n4; i += stride) {
        float4 v = s[i];
        int e0 = i << 2;                        // element index, mult of 4
        int j0 = (e0 & 15) >> 1;                // even pair index 0,2,4,6
        int pos = 2 * (j0 & 3) + (j0 >> 2);     // pos8(j0); pos8(j0+1)=pos+2
        int base = ((e0 >> 4) << 3) + pos;
        d[base]     = pack2(v.x, v.y);
        d[base + 2] = pack2(v.z, v.w);
    }
}

// ---------------------------------------------------------------------------
// fp16 mma.sync GEMM (m16n8k16). CTA tile 64x128, 128 threads (4 warps as
// 1m x 4n, warp tile 64x32 -> LDS/HMMA ratio 0.5 preserved). 4 CTAs/SM.
// K chunks of 64, 2-stage cp.async. Smem row 32 u32, granule XOR swizzle.
// PERMUTE=true modes: z=0 Q (scale incl log2e), z=1 K, z=2 V^T.
// ---------------------------------------------------------------------------
constexpr int GKU    = 512;             // u32 per global row (1024 fp16)
constexpr int KCU    = 32;              // u32 per chunk row (K=64 fp16)
constexpr int NCHUNK = 16;
constexpr int GSTR   = 32;              // u32 smem row
constexpr int ATILE  = 64 * GSTR;       // 2048 u32
constexpr int BTILE  = 128 * GSTR;      // 4096 u32
constexpr int GSTAGE = ATILE + BTILE;   // 6144 u32
constexpr int GEMM_SMEM = 2 * GSTAGE * 4;   // 49152 bytes

struct GemmT {
    const uint32_t* A[3];
    const uint32_t* W[3];
    const float*    bias[3];
    void*           out[3];
};

template <bool PERMUTE>
__global__ __launch_bounds__(128, 4) void gemm_mma_kernel(GemmT args)
{
    const uint32_t* smu = (const uint32_t*)dyn_smem;
    const uint32_t smem_base = smem_u32(dyn_smem);

    const int z = blockIdx.z;
    const uint32_t* __restrict__ A = args.A[z];
    const uint32_t* __restrict__ W = args.W[z];
    const float* __restrict__ bias = args.bias[z];

    const int tid  = threadIdx.x;
    const int wn   = tid >> 5;          // 0..3 (n-direction warp)
    const int lane = tid & 31;
    const int bn   = blockIdx.x << 7;   // N tile 128
    const int bm   = blockIdx.y << 6;   // M tile 64
    const int lrow = lane >> 2;
    const int lcol = lane & 3;

    const uint32_t* Ab = A + (size_t)bm * GKU;
    const uint32_t* Wb = W + (size_t)bn * GKU;

    const int g_row = tid >> 3;          // 0..15 (+16 per iter)
    const int g_c4  = (tid & 7) << 2;    // 0..28 (u32)

    auto issue = [&](int c, int s) {
        const uint32_t base = smem_base + (uint32_t)s * GSTAGE * 4;
        const int kb = c * KCU + g_c4;
#pragma unroll
        for (int t = 0; t < 4; ++t) {   // A: 64 rows
            int row = g_row + t * 16;
            int sc  = g_c4 ^ ((row & 3) << 3);
            cp_async16(base + (uint32_t)(row * GSTR + sc) * 4,
                       Ab + (size_t)row * GKU + kb);
        }
#pragma unroll
        for (int t = 0; t < 8; ++t) {   // B: 128 rows
            int row = g_row + t * 16;
            int sc  = g_c4 ^ ((row & 3) << 3);
            cp_async16(base + (uint32_t)(ATILE + row * GSTR + sc) * 4,
                       Wb + (size_t)row * GKU + kb);
        }
        CP_COMMIT();
    };

    float acc[4][4][4];
#pragma unroll
    for (int i = 0; i < 4; ++i)
#pragma unroll
        for (int j = 0; j < 4; ++j)
#pragma unroll
            for (int r = 0; r < 4; ++r) acc[i][j][r] = 0.f;

    issue(0, 0);

    const int sw = (lrow & 3) << 3;
    for (int c = 0; c < NCHUNK; ++c) {
        CP_WAIT0();
        __syncthreads();
        if (c + 1 < NCHUNK) issue(c + 1, (c + 1) & 1);

        const uint32_t* sa = smu + (c & 1) * GSTAGE;
        const uint32_t* sb = sa + ATILE;
#pragma unroll
        for (int kp = 0; kp < 4; ++kp) {            // k16 steps
            const int co = (kp * 8 + 2 * lcol) ^ sw;
            uint32_t af[4][4], bf[4][2];
#pragma unroll
            for (int mi = 0; mi < 4; ++mi) {
                int r0 = mi * 16 + lrow;
                uint2 lo = *(const uint2*)(sa + r0 * GSTR + co);
                uint2 hi = *(const uint2*)(sa + (r0 + 8) * GSTR + co);
                af[mi][0] = lo.x; af[mi][1] = hi.x;
                af[mi][2] = lo.y; af[mi][3] = hi.y;
            }
#pragma unroll
            for (int ni = 0; ni < 4; ++ni) {
                int n0 = wn * 32 + ni * 8 + lrow;
                uint2 b2 = *(const uint2*)(sb + n0 * GSTR + co);
                bf[ni][0] = b2.x; bf[ni][1] = b2.y;
            }
#pragma unroll
            for (int mi = 0; mi < 4; ++mi)
#pragma unroll
                for (int ni = 0; ni < 4; ++ni)
                    mma_f16(acc[mi][ni], af[mi], bf[ni]);
        }
    }

    // epilogue
    if (PERMUTE) {
        uint32_t* out = (uint32_t*)args.out[z];
        // z=0: Q scaled by 1/8 * log2(e) so softmax can use exp2
        const float scale = (z == 0) ? 0.125f * 1.44269504088896f : 1.f;
#pragma unroll
        for (int mi = 0; mi < 4; ++mi) {
            const int row0 = bm + mi * 16 + lrow;
            const int row1 = row0 + 8;
#pragma unroll
            for (int ni = 0; ni < 4; ++ni) {
                const int col = bn + wn * 32 + ni * 8 + 2 * lcol;
                float2 bv = *(const float2*)&bias[col];
                float v00 = (acc[mi][ni][0] + bv.x) * scale;
                float v01 = (acc[mi][ni][1] + bv.y) * scale;
                float v10 = (acc[mi][ni][2] + bv.x) * scale;
                float v11 = (acc[mi][ni][3] + bv.y) * scale;
                const int h  = col >> 6;
                const int hd = col & 63;
                int b0 = row0 >> 11, s0 = row0 & 2047;
                int b1 = row1 >> 11, s1 = row1 & 2047;
                if (z != 2) {
                    // pair (hd, hd+1) -> inner u32 = ((hd>>4)<<3) + 2*lcol + (ni&1)
                    int inner = ((hd >> 4) << 3) + 2 * lcol + (ni & 1);
                    size_t r0b = ((size_t)(b0 * Hc + h) * Sc + s0) * 32 + inner;
                    size_t r1b = ((size_t)(b1 * Hc + h) * Sc + s1) * 32 + inner;
                    out[r0b] = pack2(v00, v01);
                    out[r1b] = pack2(v10, v11);
                } else {
                    // V^T: pair along seq; exchange with lrow^1 neighbor
                    float p00 = __shfl_xor_sync(0xffffffffu, v00, 4);
                    float p01 = __shfl_xor_sync(0xffffffffu, v01, 4);
                    float p10 = __shfl_xor_sync(0xffffffffu, v10, 4);
                    float p11 = __shfl_xor_sync(0xffffffffu, v11, 4);
                    if ((lrow & 1) == 0) {
                        int base = ((s0 >> 4) << 3);
                        size_t vr0 = ((size_t)(b0 * Hc + h) * HDc + hd) * (Sc / 2);
                        size_t vr1 = vr0 + (Sc / 2);      // hd+1
                        out[vr0 + base + lrow]     = pack2(v00, p00);
                        out[vr0 + base + lrow + 1] = pack2(v10, p10);
                        out[vr1 + base + lrow]     = pack2(v01, p01);
                        out[vr1 + base + lrow + 1] = pack2(v11, p11);
                    }
                }
            }
        }
    } else {
        float* out = (float*)args.out[z];
#pragma unroll
        for (int mi = 0; mi < 4; ++mi) {
            const int row0 = bm + mi * 16 + lrow;
            const int row1 = row0 + 8;
#pragma unroll
            for (int ni = 0; ni < 4; ++ni) {
                const int col = bn + wn * 32 + ni * 8 + 2 * lcol;
                float2 bv = *(const float2*)&bias[col];
                float2 o0 = { acc[mi][ni][0] + bv.x, acc[mi][ni][1] + bv.y };
                float2 o1 = { acc[mi][ni][2] + bv.x, acc[mi][ni][3] + bv.y };
                *(float2*)&out[(size_t)row0 * Dc + col] = o0;
                *(float2*)&out[(size_t)row1 * Dc + col] = o1;
            }
        }
    }
}

// ---------------------------------------------------------------------------
// Flash attention (causal), fp16 m16n8k16, register-resident softmax, exp2
// domain (Q pre-scaled by log2e/8). 3-stage cp.async KV pipeline.
// P a-frags are PURE REGISTER PACKS (C-frag layout == A-frag layout).
// ---------------------------------------------------------------------------
constexpr int ASTR  = 32;                            // u32 per smem row
constexpr int KSTG  = 64 * ASTR;                     // 2048 u32 per stage
constexpr int OFF_Q = 0;                             // 128*32 = 4096
constexpr int OFF_K = OFF_Q + 128 * ASTR;            // 3 stages
constexpr int OFF_V = OFF_K + 3 * KSTG;
constexpr int ATTN_SMEM_U32 = OFF_V + 3 * KSTG;      // 16384
constexpr int ATTN_SMEM_BYTES = ATTN_SMEM_U32 * 4;   // 65536

__global__ __launch_bounds__(256, 2) void attn_mma_kernel(
    const uint32_t* __restrict__ Q, const uint32_t* __restrict__ Kt,
    const uint32_t* __restrict__ V, uint32_t* __restrict__ ctx)
{
    uint32_t* smu = (uint32_t*)dyn_smem;
    const uint32_t smem_base = smem_u32(dyn_smem);

    const int tid  = threadIdx.x;
    const int wid  = tid >> 5;
    const int lane = tid & 31;
    const int lrow = lane >> 2;
    const int lcol = lane & 3;

    const int qt = gridDim.x - 1 - blockIdx.x;
    const int bh = blockIdx.y;

    // stage Q (fp16 pair-ilv, pre-scaled incl log2e); rows = 32 u32
    const uint32_t* Qb = Q + ((size_t)bh * Sc + qt * 128) * 32;
#pragma unroll
    for (int it = 0; it < 4; ++it) {
        int i  = tid + it * 256;        // 0..1023
        int rr = i >> 3;                // 0..127
        int c4 = (i & 7) << 2;
        cp_async16(smem_base + (uint32_t)(OFF_Q + rr * ASTR +
                                          (c4 ^ ((rr & 3) << 3))) * 4,
                   Qb + rr * 32 + c4);
    }

    const uint32_t* VtB = V + (size_t)bh * HDc * (Sc / 2);

    auto issue_kv = [&](int kt, int bs) {
        const uint32_t* Kb = Kt + ((size_t)bh * Sc + kt * 64) * 32;
#pragma unroll
        for (int it = 0; it < 2; ++it) {
            int i  = tid + it * 256;    // 0..511
            int rr = i >> 3;            // 0..63
            int c4 = (i & 7) << 2;
            int sc = c4 ^ ((rr & 3) << 3);
            cp_async16(smem_base + (uint32_t)(OFF_K + bs * KSTG +
                                              rr * ASTR + sc) * 4,
                       Kb + rr * 32 + c4);
            cp_async16(smem_base + (uint32_t)(OFF_V + bs * KSTG +
                                              rr * ASTR + sc) * 4,
                       VtB + (size_t)rr * (Sc / 2) + kt * 32 + c4);
        }
        CP_COMMIT();
    };

    const int nkt = 2 * qt + 2;
    issue_kv(0, 0);                      // commit covers Q stage too
    if (1 < nkt) issue_kv(1, 1);

    float m0 = -1e30f, m1 = -1e30f, l0 = 0.f, l1 = 0.f;
    float oacc[8][4];
#pragma unroll
    for (int ni = 0; ni < 8; ++ni)
#pragma unroll
        for (int t = 0; t < 4; ++t) oacc[ni][t] = 0.f;

    const int row_g0 = qt * 128 + wid * 16 + lrow;
    const int row_g1 = row_g0 + 8;
    const bool upper = (wid < 4);
    const int sw     = (lrow & 3) << 3;

    int st = 0;
    for (int kt = 0; kt < nkt; ++kt) {
        if (kt + 1 < nkt) { CP_WAIT1(); } else { CP_WAIT0(); }
        __syncthreads();
        if (kt + 2 < nkt) {
            int s2 = st + 2; if (s2 >= 3) s2 -= 3;
            issue_kv(kt + 2, s2);
        }
        const int bs = st;
        ++st; if (st == 3) st = 0;

        if (upper && kt == 2 * qt + 1) continue;   // fully masked half-tile

        const uint32_t* sKr = smu + OFF_K + bs * KSTG;
        const uint32_t* sVr = smu + OFF_V + bs * KSTG;
        const uint32_t* sQu = smu + OFF_Q;

        // ---- S = Q @ K^T (4 k16 steps over hd=64), log2 domain ----
        float sacc[8][4];
#pragma unroll
        for (int t = 0; t < 8; ++t)
#pragma unroll
            for (int j = 0; j < 4; ++j) sacc[t][j] = 0.f;

#pragma unroll
        for (int kp = 0; kp < 4; ++kp) {
            const int co = (kp * 8 + 2 * lcol) ^ sw;
            uint32_t af[4];
            {
                int r0 = wid * 16 + lrow;
                uint2 lo = *(const uint2*)(sQu + r0 * ASTR + co);
                uint2 hi = *(const uint2*)(sQu + (r0 + 8) * ASTR + co);
                af[0] = lo.x; af[1] = hi.x; af[2] = lo.y; af[3] = hi.y;
            }
#pragma unroll
            for (int ni = 0; ni < 8; ++ni) {
                int n0 = ni * 8 + lrow;
                uint2 b2 = *(const uint2*)(sKr + n0 * ASTR + co);
                uint32_t bf[2] = { b2.x, b2.y };
                mma_f16(sacc[ni], af, bf);
            }
        }

        // ---- causal mask ----
        if (kt >= 2 * qt) {
            const int cbase = kt * 64;
#pragma unroll
            for (int t = 0; t < 8; ++t) {
                int c0 = cbase + t * 8 + 2 * lcol;
                if (c0 > row_g0)     sacc[t][0] = -1e30f;
                if (c0 + 1 > row_g0) sacc[t][1] = -1e30f;
                if (c0 > row_g1)     sacc[t][2] = -1e30f;
                if (c0 + 1 > row_g1) sacc[t][3] = -1e30f;
            }
        }

        // ---- online softmax in exp2 domain (registers) ----
        float mt0 = sacc[0][0], mt1 = sacc[0][2];
#pragma unroll
        for (int t = 0; t < 8; ++t) {
            mt0 = fmaxf(mt0, fmaxf(sacc[t][0], sacc[t][1]));
            mt1 = fmaxf(mt1, fmaxf(sacc[t][2], sacc[t][3]));
        }
        mt0 = fmaxf(mt0, __shfl_xor_sync(0xffffffffu, mt0, 1));
        mt0 = fmaxf(mt0, __shfl_xor_sync(0xffffffffu, mt0, 2));
        mt1 = fmaxf(mt1, __shfl_xor_sync(0xffffffffu, mt1, 1));
        mt1 = fmaxf(mt1, __shfl_xor_sync(0xffffffffu, mt1, 2));

        float mn0 = fmaxf(m0, mt0);
        float mn1 = fmaxf(m1, mt1);
        float c0f = exp2f(m0 - mn0);
        float c1f = exp2f(m1 - mn1);

        float ps0 = 0.f, ps1 = 0.f;
#pragma unroll
        for (int t = 0; t < 8; ++t) {
            sacc[t][0] = exp2f(sacc[t][0] - mn0);
            sacc[t][1] = exp2f(sacc[t][1] - mn0);
            sacc[t][2] = exp2f(sacc[t][2] - mn1);
            sacc[t][3] = exp2f(sacc[t][3] - mn1);
            ps0 += sacc[t][0] + sacc[t][1];
            ps1 += sacc[t][2] + sacc[t][3];
        }
        ps0 += __shfl_xor_sync(0xffffffffu, ps0, 1);
        ps0 += __shfl_xor_sync(0xffffffffu, ps0, 2);
        ps1 += __shfl_xor_sync(0xffffffffu, ps1, 1);
        ps1 += __shfl_xor_sync(0xffffffffu, ps1, 2);
        l0 = l0 * c0f + ps0;
        l1 = l1 * c1f + ps1;
        m0 = mn0; m1 = mn1;

#pragma unroll
        for (int ni = 0; ni < 8; ++ni) {
            oacc[ni][0] *= c0f; oacc[ni][1] *= c0f;
            oacc[ni][2] *= c1f; oacc[ni][3] *= c1f;
        }

        // ---- O += P @ V (P a-frags are register packs; no shuffles) ----
#pragma unroll
        for (int kp = 0; kp < 4; ++kp) {
            uint32_t af[4];
            af[0] = pack2(sacc[2 * kp][0],     sacc[2 * kp][1]);
            af[1] = pack2(sacc[2 * kp][2],     sacc[2 * kp][3]);
            af[2] = pack2(sacc[2 * kp + 1][0], sacc[2 * kp + 1][1]);
            af[3] = pack2(sacc[2 * kp + 1][2], sacc[2 * kp + 1][3]);

            const int co = (kp * 8 + 2 * lcol) ^ sw;
#pragma unroll
            for (int ni = 0; ni < 8; ++ni) {
                int n0 = ni * 8 + lrow;
                uint2 b2 = *(const uint2*)(sVr + n0 * ASTR + co);
                uint32_t bf[2] = { b2.x, b2.y };
                mma_f16(oacc[ni], af, bf);
            }
        }
    }

    // ---- epilogue: normalize, store ctx as fp16 pair-ilv ----
    const float i0 = 1.f / l0;
    const float i1 = 1.f / l1;
    const int b_ = bh >> 4;
    const int h  = bh & 15;
    const int r0 = qt * 128 + wid * 16 + lrow;
    uint32_t* outU = ctx + ((size_t)(b_ * Sc) + r0) * (Dc / 2) + h * 32;
#pragma unroll
    for (int ni = 0; ni < 8; ++ni) {
        int c0 = ni * 8 + 2 * lcol;
        int inner = ((c0 >> 4) << 3) + 2 * lcol + (ni & 1);
        outU[inner] = pack2(oacc[ni][0] * i0, oacc[ni][1] * i0);
        outU[(size_t)8 * (Dc / 2) + inner] =
            pack2(oacc[ni][2] * i1, oacc[ni][3] * i1);
    }
}

// ---------------------------------------------------------------------------
extern "C" void kernel_launch(void* const* d_in, const int* in_sizes, int n_in,
                              void* d_out, int out_size)
{
    const float* query = (const float*)d_in[0];
    const float* key   = (const float*)d_in[1];
    const float* value = (const float*)d_in[2];
    // d_in[3] = mask (causal tril) — applied analytically in attn kernel
    const float* Wq = (const float*)d_in[4];
    const float* bq = (const float*)d_in[5];
    const float* Wk = (const float*)d_in[6];
    const float* bk = (const float*)d_in[7];
    const float* Wv = (const float*)d_in[8];
    const float* bv = (const float*)d_in[9];
    const float* Wo = (const float*)d_in[10];
    const float* bo = (const float*)d_in[11];
    float* out = (float*)d_out;

    uint32_t *qp, *kp, *vp, *cp;
    uint32_t *qc, *kc, *vc, *wq, *wk, *wv, *wo;
    cudaGetSymbolAddress((void**)&qp, g_Q);
    cudaGetSymbolAddress((void**)&kp, g_K);
    cudaGetSymbolAddress((void**)&vp, g_V);
    cudaGetSymbolAddress((void**)&cp, g_ctx);
    cudaGetSymbolAddress((void**)&qc, g_qc);
    cudaGetSymbolAddress((void**)&kc, g_kc);
    cudaGetSymbolAddress((void**)&vc, g_vc);
    cudaGetSymbolAddress((void**)&wq, g_wq);
    cudaGetSymbolAddress((void**)&wk, g_wk);
    cudaGetSymbolAddress((void**)&wv, g_wv);
    cudaGetSymbolAddress((void**)&wo, g_wo);

    cudaFuncSetAttribute(gemm_mma_kernel<true>,
                         cudaFuncAttributeMaxDynamicSharedMemorySize, GEMM_SMEM);
    cudaFuncSetAttribute(gemm_mma_kernel<false>,
                         cudaFuncAttributeMaxDynamicSharedMemorySize, GEMM_SMEM);
    cudaFuncSetAttribute(attn_mma_kernel,
                         cudaFuncAttributeMaxDynamicSharedMemorySize,
                         ATTN_SMEM_BYTES);

    // prepass: convert + pair-interleave inputs and weights to fp16
    CvtArgs ca;
    ca.src[0] = (const float4*)query; ca.dst[0] = qc; ca.n4[0] = Mc * Dc / 4;
    ca.src[1] = (const float4*)key;   ca.dst[1] = kc; ca.n4[1] = Mc * Dc / 4;
    ca.src[2] = (const float4*)value; ca.dst[2] = vc; ca.n4[2] = Mc * Dc / 4;
    ca.src[3] = (const float4*)Wq;    ca.dst[3] = wq; ca.n4[3] = Dc * Dc / 4;
    ca.src[4] = (const float4*)Wk;    ca.dst[4] = wk; ca.n4[4] = Dc * Dc / 4;
    ca.src[5] = (const float4*)Wv;    ca.dst[5] = wv; ca.n4[5] = Dc * Dc / 4;
    ca.src[6] = (const float4*)Wo;    ca.dst[6] = wo; ca.n4[6] = Dc * Dc / 4;
    cvt_kernel<<<dim3(512, 7), 256>>>(ca);

    // batched QKV projections (M tiles of 64 -> fine-grained waves)
    GemmT qkv;
    qkv.A[0] = qc;  qkv.A[1] = kc;  qkv.A[2] = vc;
    qkv.W[0] = wq;  qkv.W[1] = wk;  qkv.W[2] = wv;
    qkv.bias[0] = bq; qkv.bias[1] = bk; qkv.bias[2] = bv;
    qkv.out[0] = qp;  qkv.out[1] = kp;  qkv.out[2] = vp;
    gemm_mma_kernel<true><<<dim3(Dc / 128, Mc / 64, 3), 128, GEMM_SMEM>>>(qkv);

    attn_mma_kernel<<<dim3(Sc / 128, Bc * Hc), 256, ATTN_SMEM_BYTES>>>(qp, kp, vp, cp);

    // O projection
    GemmT og;
    og.A[0] = cp; og.W[0] = wo; og.bias[0] = bo; og.out[0] = out;
    og.A[1] = og.A[2] = cp; og.W[1] = og.W[2] = wo;
    og.bias[1] = og.bias[2] = bo; og.out[1] = og.out[2] = out;
    gemm_mma_kernel<false><<<dim3(Dc / 128, Mc / 64, 1), 128, GEMM_SMEM>>>(og);
}

// round 17
// speedup vs baseline: 1.4598x; 1.4598x over previous
#include <cuda_runtime.h>
#include <cuda_fp16.h>
#include <cstdint>

// Problem constants
constexpr int Bc  = 2;
constexpr int Sc  = 2048;
constexpr int Dc  = 1024;
constexpr int Hc  = 16;
constexpr int HDc = 64;
constexpr int Mc  = Bc * Sc;

// Scratch (__device__ globals). All fp16 packed as u32 (=2 fp16 along k),
// pair-interleaved within 16-k groups: pair j (j=0..7) at pos8(j)=2*(j&3)+(j>>2)
// so pairs {j, j+4} are adjacent -> fragment loads are single LDS.64.
__device__ uint32_t g_Q[Bc * Hc * Sc * HDc / 2];   // head-major, scaled by 0.125*log2e
__device__ uint32_t g_K[Bc * Hc * Sc * HDc / 2];   // head-major
__device__ uint32_t g_V[Bc * Hc * Sc * HDc / 2];   // TRANSPOSED [bh*64+hd][s]
__device__ uint32_t g_ctx[Mc * Dc / 2];
__device__ uint32_t g_qc[Mc * Dc / 2];             // converted inputs
__device__ uint32_t g_kc[Mc * Dc / 2];
__device__ uint32_t g_vc[Mc * Dc / 2];
__device__ uint32_t g_wq[Dc * Dc / 2];
__device__ uint32_t g_wk[Dc * Dc / 2];
__device__ uint32_t g_wv[Dc * Dc / 2];
__device__ uint32_t g_wo[Dc * Dc / 2];

extern __shared__ __align__(1024) char dyn_smem[];

// ---------------------------------------------------------------------------
// helpers
// ---------------------------------------------------------------------------
__device__ __forceinline__ uint32_t smem_u32(const void* p) {
    uint32_t a;
    asm("{ .reg .u64 t; cvta.to.shared.u64 t, %1; cvt.u32.u64 %0, t; }"
        : "=r"(a) : "l"(p));
    return a;
}

__device__ __forceinline__ uint32_t pack2(float a, float b) {
    __half2 h = __floats2half2_rn(a, b);
    return *reinterpret_cast<uint32_t*>(&h);
}

__device__ __forceinline__ void mma_f16(float* d, const uint32_t* a,
                                        const uint32_t* b) {
    asm volatile(
        "mma.sync.aligned.m16n8k16.row.col.f32.f16.f16.f32 "
        "{%0,%1,%2,%3}, {%4,%5,%6,%7}, {%8,%9}, {%0,%1,%2,%3};"
        : "+f"(d[0]), "+f"(d[1]), "+f"(d[2]), "+f"(d[3])
        : "r"(a[0]), "r"(a[1]), "r"(a[2]), "r"(a[3]), "r"(b[0]), "r"(b[1]));
}

__device__ __forceinline__ void cp_async16(uint32_t saddr, const void* g) {
    asm volatile("cp.async.cg.shared.global [%0], [%1], 16;"
                 :: "r"(saddr), "l"(g));
}
#define CP_COMMIT() asm volatile("cp.async.commit_group;" ::: "memory")
#define CP_WAIT0()  asm volatile("cp.async.wait_group 0;" ::: "memory")
#define CP_WAIT1()  asm volatile("cp.async.wait_group 1;" ::: "memory")

// ---------------------------------------------------------------------------
// Prepass: fp32 -> fp16 pairs, pair-interleaved (rows multiple of 16 elems)
// ---------------------------------------------------------------------------
struct CvtArgs {
    const float4* src[7];
    uint32_t*     dst[7];
    int           n4[7];
};

__global__ __launch_bounds__(256) void cvt_kernel(CvtArgs a)
{
    const int z = blockIdx.y;
    const float4* s = a.src[z];
    uint32_t* d = a.dst[z];
    const int n4 = a.n4[z];
    const int stride = gridDim.x * blockDim.x;
    for (int i = blockIdx.x * blockDim.x + threadIdx.x; i < n4; i += stride) {
        float4 v = s[i];
        int e0 = i << 2;                        // element index, mult of 4
        int j0 = (e0 & 15) >> 1;                // even pair index 0,2,4,6
        int pos = 2 * (j0 & 3) + (j0 >> 2);     // pos8(j0); pos8(j0+1)=pos+2
        int base = ((e0 >> 4) << 3) + pos;
        d[base]     = pack2(v.x, v.y);
        d[base + 2] = pack2(v.z, v.w);
    }
}

// ---------------------------------------------------------------------------
// fp16 mma.sync GEMM (m16n8k16). CTA tile 128x128, 8 warps as 2m x 4n,
// warp tile 64x32 (measured-optimal shape). K chunks of 64, 3-stage cp.async.
// Smem row 32 u32, granule XOR swizzle -> conflict-free LDS.64 frag loads.
// PERMUTE=true modes: z=0 Q (scale incl log2e), z=1 K, z=2 V^T.
// ---------------------------------------------------------------------------
constexpr int GKU    = 512;             // u32 per global row (1024 fp16)
constexpr int KCU    = 32;              // u32 per chunk row (K=64 fp16)
constexpr int NCHUNK = 16;
constexpr int GSTR   = 32;              // u32 smem row
constexpr int GTILE  = 128 * GSTR;      // 4096 u32
constexpr int GSTAGE = 2 * GTILE;       // 8192 u32 (A+B)
constexpr int GEMM_SMEM = 3 * GSTAGE * 4;   // 98304 bytes

struct GemmT {
    const uint32_t* A[3];
    const uint32_t* W[3];
    const float*    bias[3];
    void*           out[3];
};

template <bool PERMUTE>
__global__ __launch_bounds__(256, 2) void gemm_mma_kernel(GemmT args)
{
    const uint32_t* smu = (const uint32_t*)dyn_smem;
    const uint32_t smem_base = smem_u32(dyn_smem);

    const int z = blockIdx.z;
    const uint32_t* __restrict__ A = args.A[z];
    const uint32_t* __restrict__ W = args.W[z];
    const float* __restrict__ bias = args.bias[z];

    const int tid  = threadIdx.x;
    const int wid  = tid >> 5;
    const int lane = tid & 31;
    const int wm   = wid >> 2;          // 0..1
    const int wn   = wid & 3;           // 0..3
    const int bn   = blockIdx.x << 7;
    const int bm   = blockIdx.y << 7;
    const int lrow = lane >> 2;
    const int lcol = lane & 3;

    const uint32_t* Ab = A + (size_t)bm * GKU;
    const uint32_t* Wb = W + (size_t)bn * GKU;

    const int g_row = tid >> 3;          // 0..31 (+32 per iter)
    const int g_c4  = (tid & 7) << 2;    // 0..28 (u32)

    auto issue = [&](int c, int s) {
        const uint32_t base = smem_base + (uint32_t)s * GSTAGE * 4;
        const int kb = c * KCU + g_c4;
#pragma unroll
        for (int t = 0; t < 4; ++t) {
            int row = g_row + t * 32;
            int sc  = g_c4 ^ ((row & 3) << 3);
            cp_async16(base + (uint32_t)(row * GSTR + sc) * 4,
                       Ab + (size_t)row * GKU + kb);
            cp_async16(base + (uint32_t)(GTILE + row * GSTR + sc) * 4,
                       Wb + (size_t)row * GKU + kb);
        }
        CP_COMMIT();
    };

    float acc[4][4][4];
#pragma unroll
    for (int i = 0; i < 4; ++i)
#pragma unroll
        for (int j = 0; j < 4; ++j)
#pragma unroll
            for (int r = 0; r < 4; ++r) acc[i][j][r] = 0.f;

    issue(0, 0);
    issue(1, 1);

    const int sw = (lrow & 3) << 3;
    int st = 0;
    for (int c = 0; c < NCHUNK; ++c) {
        if (c < NCHUNK - 1) { CP_WAIT1(); } else { CP_WAIT0(); }
        __syncthreads();
        if (c + 2 < NCHUNK) {
            int s2 = st + 2; if (s2 >= 3) s2 -= 3;
            issue(c + 2, s2);
        }

        const uint32_t* sa = smu + st * GSTAGE;
        const uint32_t* sb = sa + GTILE;
#pragma unroll
        for (int kp = 0; kp < 4; ++kp) {            // k16 steps
            const int co = (kp * 8 + 2 * lcol) ^ sw;
            uint32_t af[4][4], bf[4][2];
#pragma unroll
            for (int mi = 0; mi < 4; ++mi) {
                int r0 = wm * 64 + mi * 16 + lrow;
                uint2 lo = *(const uint2*)(sa + r0 * GSTR + co);
                uint2 hi = *(const uint2*)(sa + (r0 + 8) * GSTR + co);
                af[mi][0] = lo.x; af[mi][1] = hi.x;
                af[mi][2] = lo.y; af[mi][3] = hi.y;
            }
#pragma unroll
            for (int ni = 0; ni < 4; ++ni) {
                int n0 = wn * 32 + ni * 8 + lrow;
                uint2 b2 = *(const uint2*)(sb + n0 * GSTR + co);
                bf[ni][0] = b2.x; bf[ni][1] = b2.y;
            }
#pragma unroll
            for (int mi = 0; mi < 4; ++mi)
#pragma unroll
                for (int ni = 0; ni < 4; ++ni)
                    mma_f16(acc[mi][ni], af[mi], bf[ni]);
        }
        ++st; if (st == 3) st = 0;
    }

    // epilogue (bias pre-hoisted per ni)
    float2 bvv[4];
#pragma unroll
    for (int ni = 0; ni < 4; ++ni) {
        const int col = bn + wn * 32 + ni * 8 + 2 * lcol;
        bvv[ni].x = __ldg(&bias[col]);
        bvv[ni].y = __ldg(&bias[col + 1]);
    }

    if (PERMUTE) {
        uint32_t* out = (uint32_t*)args.out[z];
        // z=0: Q scaled by 1/8 * log2(e) so softmax can use exp2
        const float scale = (z == 0) ? 0.125f * 1.44269504088896f : 1.f;
#pragma unroll
        for (int mi = 0; mi < 4; ++mi) {
            const int row0 = bm + wm * 64 + mi * 16 + lrow;
            const int row1 = row0 + 8;
#pragma unroll
            for (int ni = 0; ni < 4; ++ni) {
                const int col = bn + wn * 32 + ni * 8 + 2 * lcol;
                float v00 = (acc[mi][ni][0] + bvv[ni].x) * scale;
                float v01 = (acc[mi][ni][1] + bvv[ni].y) * scale;
                float v10 = (acc[mi][ni][2] + bvv[ni].x) * scale;
                float v11 = (acc[mi][ni][3] + bvv[ni].y) * scale;
                const int h  = col >> 6;
                const int hd = col & 63;
                int b0 = row0 >> 11, s0 = row0 & 2047;
                int b1 = row1 >> 11, s1 = row1 & 2047;
                if (z != 2) {
                    // pair (hd, hd+1) -> inner u32 = ((hd>>4)<<3) + 2*lcol + (ni&1)
                    int inner = ((hd >> 4) << 3) + 2 * lcol + (ni & 1);
                    size_t r0b = ((size_t)(b0 * Hc + h) * Sc + s0) * 32 + inner;
                    size_t r1b = ((size_t)(b1 * Hc + h) * Sc + s1) * 32 + inner;
                    out[r0b] = pack2(v00, v01);
                    out[r1b] = pack2(v10, v11);
                } else {
                    // V^T: pair along seq; exchange with lrow^1 neighbor
                    float p00 = __shfl_xor_sync(0xffffffffu, v00, 4);
                    float p01 = __shfl_xor_sync(0xffffffffu, v01, 4);
                    float p10 = __shfl_xor_sync(0xffffffffu, v10, 4);
                    float p11 = __shfl_xor_sync(0xffffffffu, v11, 4);
                    if ((lrow & 1) == 0) {
                        int base = ((s0 >> 4) << 3);
                        size_t vr0 = ((size_t)(b0 * Hc + h) * HDc + hd) * (Sc / 2);
                        size_t vr1 = vr0 + (Sc / 2);      // hd+1
                        out[vr0 + base + lrow]     = pack2(v00, p00);
                        out[vr0 + base + lrow + 1] = pack2(v10, p10);
                        out[vr1 + base + lrow]     = pack2(v01, p01);
                        out[vr1 + base + lrow + 1] = pack2(v11, p11);
                    }
                }
            }
        }
    } else {
        float* out = (float*)args.out[z];
#pragma unroll
        for (int mi = 0; mi < 4; ++mi) {
            const int row0 = bm + wm * 64 + mi * 16 + lrow;
            const int row1 = row0 + 8;
#pragma unroll
            for (int ni = 0; ni < 4; ++ni) {
                const int col = bn + wn * 32 + ni * 8 + 2 * lcol;
                float2 o0 = { acc[mi][ni][0] + bvv[ni].x, acc[mi][ni][1] + bvv[ni].y };
                float2 o1 = { acc[mi][ni][2] + bvv[ni].x, acc[mi][ni][3] + bvv[ni].y };
                *(float2*)&out[(size_t)row0 * Dc + col] = o0;
                *(float2*)&out[(size_t)row1 * Dc + col] = o1;
            }
        }
    }
}

// ---------------------------------------------------------------------------
// Flash attention (causal), fp16 m16n8k16, register-resident softmax, exp2
// domain (Q pre-scaled by log2e/8). 3-stage cp.async KV pipeline.
// P a-frags are PURE REGISTER PACKS (C-frag layout == A-frag layout).
// ---------------------------------------------------------------------------
constexpr int ASTR  = 32;                            // u32 per smem row
constexpr int KSTG  = 64 * ASTR;                     // 2048 u32 per stage
constexpr int OFF_Q = 0;                             // 128*32 = 4096
constexpr int OFF_K = OFF_Q + 128 * ASTR;            // 3 stages
constexpr int OFF_V = OFF_K + 3 * KSTG;
constexpr int ATTN_SMEM_U32 = OFF_V + 3 * KSTG;      // 16384
constexpr int ATTN_SMEM_BYTES = ATTN_SMEM_U32 * 4;   // 65536

__global__ __launch_bounds__(256, 2) void attn_mma_kernel(
    const uint32_t* __restrict__ Q, const uint32_t* __restrict__ Kt,
    const uint32_t* __restrict__ V, uint32_t* __restrict__ ctx)
{
    uint32_t* smu = (uint32_t*)dyn_smem;
    const uint32_t smem_base = smem_u32(dyn_smem);

    const int tid  = threadIdx.x;
    const int wid  = tid >> 5;
    const int lane = tid & 31;
    const int lrow = lane >> 2;
    const int lcol = lane & 3;

    const int qt = gridDim.x - 1 - blockIdx.x;
    const int bh = blockIdx.y;

    // stage Q (fp16 pair-ilv, pre-scaled incl log2e); rows = 32 u32
    const uint32_t* Qb = Q + ((size_t)bh * Sc + qt * 128) * 32;
#pragma unroll
    for (int it = 0; it < 4; ++it) {
        int i  = tid + it * 256;        // 0..1023
        int rr = i >> 3;                // 0..127
        int c4 = (i & 7) << 2;
        cp_async16(smem_base + (uint32_t)(OFF_Q + rr * ASTR +
                                          (c4 ^ ((rr & 3) << 3))) * 4,
                   Qb + rr * 32 + c4);
    }

    const uint32_t* VtB = V + (size_t)bh * HDc * (Sc / 2);

    auto issue_kv = [&](int kt, int bs) {
        const uint32_t* Kb = Kt + ((size_t)bh * Sc + kt * 64) * 32;
#pragma unroll
        for (int it = 0; it < 2; ++it) {
            int i  = tid + it * 256;    // 0..511
            int rr = i >> 3;            // 0..63
            int c4 = (i & 7) << 2;
            int sc = c4 ^ ((rr & 3) << 3);
            cp_async16(smem_base + (uint32_t)(OFF_K + bs * KSTG +
                                              rr * ASTR + sc) * 4,
                       Kb + rr * 32 + c4);
            cp_async16(smem_base + (uint32_t)(OFF_V + bs * KSTG +
                                              rr * ASTR + sc) * 4,
                       VtB + (size_t)rr * (Sc / 2) + kt * 32 + c4);
        }
        CP_COMMIT();
    };

    const int nkt = 2 * qt + 2;
    issue_kv(0, 0);                      // commit covers Q stage too
    if (1 < nkt) issue_kv(1, 1);

    float m0 = -1e30f, m1 = -1e30f, l0 = 0.f, l1 = 0.f;
    float oacc[8][4];
#pragma unroll
    for (int ni = 0; ni < 8; ++ni)
#pragma unroll
        for (int t = 0; t < 4; ++t) oacc[ni][t] = 0.f;

    const int row_g0 = qt * 128 + wid * 16 + lrow;
    const int row_g1 = row_g0 + 8;
    const bool upper = (wid < 4);
    const int sw     = (lrow & 3) << 3;

    int st = 0;
    for (int kt = 0; kt < nkt; ++kt) {
        if (kt + 1 < nkt) { CP_WAIT1(); } else { CP_WAIT0(); }
        __syncthreads();
        if (kt + 2 < nkt) {
            int s2 = st + 2; if (s2 >= 3) s2 -= 3;
            issue_kv(kt + 2, s2);
        }
        const int bs = st;
        ++st; if (st == 3) st = 0;

        if (upper && kt == 2 * qt + 1) continue;   // fully masked half-tile

        const uint32_t* sKr = smu + OFF_K + bs * KSTG;
        const uint32_t* sVr = smu + OFF_V + bs * KSTG;
        const uint32_t* sQu = smu + OFF_Q;

        // ---- S = Q @ K^T (4 k16 steps over hd=64), log2 domain ----
        float sacc[8][4];
#pragma unroll
        for (int t = 0; t < 8; ++t)
#pragma unroll
            for (int j = 0; j < 4; ++j) sacc[t][j] = 0.f;

#pragma unroll
        for (int kp = 0; kp < 4; ++kp) {
            const int co = (kp * 8 + 2 * lcol) ^ sw;
            uint32_t af[4];
            {
                int r0 = wid * 16 + lrow;
                uint2 lo = *(const uint2*)(sQu + r0 * ASTR + co);
                uint2 hi = *(const uint2*)(sQu + (r0 + 8) * ASTR + co);
                af[0] = lo.x; af[1] = hi.x; af[2] = lo.y; af[3] = hi.y;
            }
#pragma unroll
            for (int ni = 0; ni < 8; ++ni) {
                int n0 = ni * 8 + lrow;
                uint2 b2 = *(const uint2*)(sKr + n0 * ASTR + co);
                uint32_t bf[2] = { b2.x, b2.y };
                mma_f16(sacc[ni], af, bf);
            }
        }

        // ---- causal mask ----
        if (kt >= 2 * qt) {
            const int cbase = kt * 64;
#pragma unroll
            for (int t = 0; t < 8; ++t) {
                int c0 = cbase + t * 8 + 2 * lcol;
                if (c0 > row_g0)     sacc[t][0] = -1e30f;
                if (c0 + 1 > row_g0) sacc[t][1] = -1e30f;
                if (c0 > row_g1)     sacc[t][2] = -1e30f;
                if (c0 + 1 > row_g1) sacc[t][3] = -1e30f;
            }
        }

        // ---- online softmax in exp2 domain (registers) ----
        float mt0 = sacc[0][0], mt1 = sacc[0][2];
#pragma unroll
        for (int t = 0; t < 8; ++t) {
            mt0 = fmaxf(mt0, fmaxf(sacc[t][0], sacc[t][1]));
            mt1 = fmaxf(mt1, fmaxf(sacc[t][2], sacc[t][3]));
        }
        mt0 = fmaxf(mt0, __shfl_xor_sync(0xffffffffu, mt0, 1));
        mt0 = fmaxf(mt0, __shfl_xor_sync(0xffffffffu, mt0, 2));
        mt1 = fmaxf(mt1, __shfl_xor_sync(0xffffffffu, mt1, 1));
        mt1 = fmaxf(mt1, __shfl_xor_sync(0xffffffffu, mt1, 2));

        float mn0 = fmaxf(m0, mt0);
        float mn1 = fmaxf(m1, mt1);
        float c0f = exp2f(m0 - mn0);
        float c1f = exp2f(m1 - mn1);

        float ps0 = 0.f, ps1 = 0.f;
#pragma unroll
        for (int t = 0; t < 8; ++t) {
            sacc[t][0] = exp2f(sacc[t][0] - mn0);
            sacc[t][1] = exp2f(sacc[t][1] - mn0);
            sacc[t][2] = exp2f(sacc[t][2] - mn1);
            sacc[t][3] = exp2f(sacc[t][3] - mn1);
            ps0 += sacc[t][0] + sacc[t][1];
            ps1 += sacc[t][2] + sacc[t][3];
        }
        ps0 += __shfl_xor_sync(0xffffffffu, ps0, 1);
        ps0 += __shfl_xor_sync(0xffffffffu, ps0, 2);
        ps1 += __shfl_xor_sync(0xffffffffu, ps1, 1);
        ps1 += __shfl_xor_sync(0xffffffffu, ps1, 2);
        l0 = l0 * c0f + ps0;
        l1 = l1 * c1f + ps1;
        m0 = mn0; m1 = mn1;

#pragma unroll
        for (int ni = 0; ni < 8; ++ni) {
            oacc[ni][0] *= c0f; oacc[ni][1] *= c0f;
            oacc[ni][2] *= c1f; oacc[ni][3] *= c1f;
        }

        // ---- O += P @ V (P a-frags are register packs; no shuffles) ----
#pragma unroll
        for (int kp = 0; kp < 4; ++kp) {
            uint32_t af[4];
            af[0] = pack2(sacc[2 * kp][0],     sacc[2 * kp][1]);
            af[1] = pack2(sacc[2 * kp][2],     sacc[2 * kp][3]);
            af[2] = pack2(sacc[2 * kp + 1][0], sacc[2 * kp + 1][1]);
            af[3] = pack2(sacc[2 * kp + 1][2], sacc[2 * kp + 1][3]);

            const int co = (kp * 8 + 2 * lcol) ^ sw;
#pragma unroll
            for (int ni = 0; ni < 8; ++ni) {
                int n0 = ni * 8 + lrow;
                uint2 b2 = *(const uint2*)(sVr + n0 * ASTR + co);
                uint32_t bf[2] = { b2.x, b2.y };
                mma_f16(oacc[ni], af, bf);
            }
        }
    }

    // ---- epilogue: normalize, store ctx as fp16 pair-ilv ----
    const float i0 = 1.f / l0;
    const float i1 = 1.f / l1;
    const int b_ = bh >> 4;
    const int h  = bh & 15;
    const int r0 = qt * 128 + wid * 16 + lrow;
    uint32_t* outU = ctx + ((size_t)(b_ * Sc) + r0) * (Dc / 2) + h * 32;
#pragma unroll
    for (int ni = 0; ni < 8; ++ni) {
        int c0 = ni * 8 + 2 * lcol;
        int inner = ((c0 >> 4) << 3) + 2 * lcol + (ni & 1);
        outU[inner] = pack2(oacc[ni][0] * i0, oacc[ni][1] * i0);
        outU[(size_t)8 * (Dc / 2) + inner] =
            pack2(oacc[ni][2] * i1, oacc[ni][3] * i1);
    }
}

// ---------------------------------------------------------------------------
extern "C" void kernel_launch(void* const* d_in, const int* in_sizes, int n_in,
                              void* d_out, int out_size)
{
    const float* query = (const float*)d_in[0];
    const float* key   = (const float*)d_in[1];
    const float* value = (const float*)d_in[2];
    // d_in[3] = mask (causal tril) — applied analytically in attn kernel
    const float* Wq = (const float*)d_in[4];
    const float* bq = (const float*)d_in[5];
    const float* Wk = (const float*)d_in[6];
    const float* bk = (const float*)d_in[7];
    const float* Wv = (const float*)d_in[8];
    const float* bv = (const float*)d_in[9];
    const float* Wo = (const float*)d_in[10];
    const float* bo = (const float*)d_in[11];
    float* out = (float*)d_out;

    uint32_t *qp, *kp, *vp, *cp;
    uint32_t *qc, *kc, *vc, *wq, *wk, *wv, *wo;
    cudaGetSymbolAddress((void**)&qp, g_Q);
    cudaGetSymbolAddress((void**)&kp, g_K);
    cudaGetSymbolAddress((void**)&vp, g_V);
    cudaGetSymbolAddress((void**)&cp, g_ctx);
    cudaGetSymbolAddress((void**)&qc, g_qc);
    cudaGetSymbolAddress((void**)&kc, g_kc);
    cudaGetSymbolAddress((void**)&vc, g_vc);
    cudaGetSymbolAddress((void**)&wq, g_wq);
    cudaGetSymbolAddress((void**)&wk, g_wk);
    cudaGetSymbolAddress((void**)&wv, g_wv);
    cudaGetSymbolAddress((void**)&wo, g_wo);

    cudaFuncSetAttribute(gemm_mma_kernel<true>,
                         cudaFuncAttributeMaxDynamicSharedMemorySize, GEMM_SMEM);
    cudaFuncSetAttribute(gemm_mma_kernel<false>,
                         cudaFuncAttributeMaxDynamicSharedMemorySize, GEMM_SMEM);
    cudaFuncSetAttribute(attn_mma_kernel,
                         cudaFuncAttributeMaxDynamicSharedMemorySize,
                         ATTN_SMEM_BYTES);

    // prepass: convert + pair-interleave inputs and weights to fp16
    CvtArgs ca;
    ca.src[0] = (const float4*)query; ca.dst[0] = qc; ca.n4[0] = Mc * Dc / 4;
    ca.src[1] = (const float4*)key;   ca.dst[1] = kc; ca.n4[1] = Mc * Dc / 4;
    ca.src[2] = (const float4*)value; ca.dst[2] = vc; ca.n4[2] = Mc * Dc / 4;
    ca.src[3] = (const float4*)Wq;    ca.dst[3] = wq; ca.n4[3] = Dc * Dc / 4;
    ca.src[4] = (const float4*)Wk;    ca.dst[4] = wk; ca.n4[4] = Dc * Dc / 4;
    ca.src[5] = (const float4*)Wv;    ca.dst[5] = wv; ca.n4[5] = Dc * Dc / 4;
    ca.src[6] = (const float4*)Wo;    ca.dst[6] = wo; ca.n4[6] = Dc * Dc / 4;
    cvt_kernel<<<dim3(768, 7), 256>>>(ca);

    // batched QKV projections
    GemmT qkv;
    qkv.A[0] = qc;  qkv.A[1] = kc;  qkv.A[2] = vc;
    qkv.W[0] = wq;  qkv.W[1] = wk;  qkv.W[2] = wv;
    qkv.bias[0] = bq; qkv.bias[1] = bk; qkv.bias[2] = bv;
    qkv.out[0] = qp;  qkv.out[1] = kp;  qkv.out[2] = vp;
    gemm_mma_kernel<true><<<dim3(Dc / 128, Mc / 128, 3), 256, GEMM_SMEM>>>(qkv);

    attn_mma_kernel<<<dim3(Sc / 128, Bc * Hc), 256, ATTN_SMEM_BYTES>>>(qp, kp, vp, cp);

    // O projection
    GemmT og;
    og.A[0] = cp; og.W[0] = wo; og.bias[0] = bo; og.out[0] = out;
    og.A[1] = og.A[2] = cp; og.W[1] = og.W[2] = wo;
    og.bias[1] = og.bias[2] = bo; og.out[1] = og.out[2] = out;
    gemm_mma_kernel<false><<<dim3(Dc / 128, Mc / 128, 1), 256, GEMM_SMEM>>>(og);
}